// round 4
// baseline (speedup 1.0000x reference)
#include <cuda_runtime.h>
#include <cstdint>

// ---------------- problem constants ----------------
#define AT   8192            // tokens (B*S)
#define DD   1024            // model dim
#define EE   8               // experts
#define HH   2816            // ffn hidden
#define CAPC 2560            // capacity per expert
#define NASS (AT * 2)        // assignments (K=2)

// ---------------- scratch (device globals; no allocs allowed) ----------------
__device__ int   g_assign_e[NASS];
__device__ float g_assign_w[NASS];
__device__ int   g_assign_pos[NASS];
__device__ int   g_tok[EE * CAPC];
__device__ float g_wslot[EE * CAPC];
__device__ int   g_cnt[EE];
__device__ int   g_lim[EE];
__device__ float g_hidden[(size_t)EE * CAPC * HH];
__device__ float g_y[(size_t)EE * CAPC * DD];

// ---------------- small helpers ----------------
__device__ __forceinline__ unsigned smem_u32(const void* p) {
    return (unsigned)__cvta_generic_to_shared(p);
}
__device__ __forceinline__ void cp_async16(void* dst, const void* src) {
    asm volatile("cp.async.cg.shared.global [%0], [%1], 16;\n"
                 :: "r"(smem_u32(dst)), "l"(src));
}
__device__ __forceinline__ void cp_commit() {
    asm volatile("cp.async.commit_group;\n");
}
template <int N>
__device__ __forceinline__ void cp_wait() {
    asm volatile("cp.async.wait_group %0;\n" :: "n"(N));
}
__device__ __forceinline__ uint32_t f2tf(float f) {
    uint32_t u;
    asm volatile("cvt.rna.tf32.f32 %0, %1;\n" : "=r"(u) : "f"(f));
    return u;
}
__device__ __forceinline__ void mma8(float* c, const uint32_t* a, const uint32_t* b) {
    asm volatile(
        "mma.sync.aligned.m16n8k8.row.col.f32.tf32.tf32.f32 "
        "{%0,%1,%2,%3}, {%4,%5,%6,%7}, {%8,%9}, {%0,%1,%2,%3};\n"
        : "+f"(c[0]), "+f"(c[1]), "+f"(c[2]), "+f"(c[3])
        : "r"(a[0]), "r"(a[1]), "r"(a[2]), "r"(a[3]), "r"(b[0]), "r"(b[1]));
}
__device__ __forceinline__ float swiglu_act(float a, float b) {
    return (a / (1.f + __expf(-a))) * b;
}

// ---------------- 1) router: logits, top-2, renormalized weights ----------------
__global__ __launch_bounds__(256) void moe_router(const float* __restrict__ x,
                                                  const float* __restrict__ wr) {
    __shared__ float ws[EE * DD];  // 32 KB
    for (int i = threadIdx.x; i < EE * DD; i += 256) ws[i] = wr[i];
    __syncthreads();

    int lane = threadIdx.x & 31, w = threadIdx.x >> 5;
    int t = blockIdx.x * 8 + w;
    const float* xr = x + (size_t)t * DD;

    float acc[EE];
#pragma unroll
    for (int e = 0; e < EE; e++) acc[e] = 0.f;
    for (int d = lane; d < DD; d += 32) {
        float xv = xr[d];
#pragma unroll
        for (int e = 0; e < EE; e++) acc[e] += xv * ws[e * DD + d];
    }
#pragma unroll
    for (int off = 16; off > 0; off >>= 1) {
#pragma unroll
        for (int e = 0; e < EE; e++)
            acc[e] += __shfl_xor_sync(0xffffffffu, acc[e], off);
    }
    if (lane == 0) {
        float best = -1e30f, sec = -1e30f;
        int bi = 0, si = 0;
#pragma unroll
        for (int e = 0; e < EE; e++) {
            float l = acc[e];
            if (l > best) { sec = best; si = bi; best = l; bi = e; }
            else if (l > sec) { sec = l; si = e; }
        }
        // renormalized top-2 softmax weights: w0 = sigmoid(l0 - l1)
        float w0 = 1.f / (1.f + expf(sec - best));
        g_assign_e[2 * t]     = bi; g_assign_w[2 * t]     = w0;
        g_assign_e[2 * t + 1] = si; g_assign_w[2 * t + 1] = 1.f - w0;
    }
}

// ---------------- 1b) sizes: per-expert histogram -> reference's rank-offset limits ----
// Reference rank formula: rank = sorted_pos - num_groups_started + 1, i.e. for the
// r-th assignment of expert e:  rank = S_e + r - G_e + 1  (S_e = assignments of
// earlier experts, G_e = nonempty experts <= e). Survives iff rank < CAP
// =>  r < lim_e = CAP - (S_e - G_e + 1).
__global__ void moe_sizes() {
    __shared__ int hist[EE];
    int tid = threadIdx.x;
    if (tid < EE) hist[tid] = 0;
    __syncthreads();
    for (int i = tid; i < NASS; i += blockDim.x)
        atomicAdd(&hist[g_assign_e[i]], 1);
    __syncthreads();
    if (tid == 0) {
        int S = 0, G = 0;
        for (int e = 0; e < EE; e++) {
            int sz = hist[e];
            int lim = 0;
            if (sz > 0) {
                G++;
                lim = CAPC - (S - G + 1);
                if (lim < 0) lim = 0;
                if (lim > CAPC) lim = CAPC;
            }
            g_lim[e] = lim;
            S += sz;
        }
    }
}

// ---------------- 2) dispatch: stable rank within expert, offset-capacity drop -------
__global__ __launch_bounds__(256) void moe_dispatch() {
    int e = blockIdx.x;          // one block per expert
    int tid = threadIdx.x;
    int lane = tid & 31, wid = tid >> 5;
    int lim = g_lim[e];
    __shared__ int warpsum[8];
    int carry = 0;
    for (int chunk = 0; chunk < NASS / 256; chunk++) {
        int i = chunk * 256 + tid;
        bool flag = (g_assign_e[i] == e);
        unsigned mask = __ballot_sync(0xffffffffu, flag);
        int wexcl = __popc(mask & ((1u << lane) - 1u));
        if (lane == 0) warpsum[wid] = __popc(mask);
        __syncthreads();
        int bexcl = 0, total = 0;
#pragma unroll
        for (int w = 0; w < 8; w++) {
            int s = warpsum[w];
            if (w < wid) bexcl += s;
            total += s;
        }
        if (flag) {
            int rank = carry + bexcl + wexcl;
            if (rank < lim) {
                g_tok[e * CAPC + rank]   = i >> 1;       // token id
                g_wslot[e * CAPC + rank] = g_assign_w[i];
                g_assign_pos[i] = rank;
            } else {
                g_assign_pos[i] = -1;                    // dropped
            }
        }
        carry += total;
        __syncthreads();
    }
    if (tid == 0) g_cnt[e] = carry < lim ? carry : lim;
}

// ---------------- 3) fused GEMM1: h1 = X@W1^T, h3 = X@W3^T, hidden = silu(h1)*h3 ----
#define BM   128
#define BN1  64
#define BK   32
#define LDT  36
#define NST  3
#define SS1  ((BM + 2 * BN1) * LDT)

__global__ __launch_bounds__(256) void moe_gemm1(const float* __restrict__ x,
                                                 const float* __restrict__ w1,
                                                 const float* __restrict__ w3) {
    int e = blockIdx.z;
    int cnt = g_cnt[e];
    int m0 = blockIdx.y * BM;
    if (m0 >= cnt) return;
    int n0 = blockIdx.x * BN1;

    extern __shared__ float sm[];
    __shared__ int tokSm[BM];
    int tid = threadIdx.x;
    for (int m = tid; m < BM; m += 256) {
        int r = m0 + m;
        if (r > cnt - 1) r = cnt - 1;       // clamp: duplicate rows computed, never combined
        tokSm[m] = g_tok[e * CAPC + r];
    }
    __syncthreads();

    const float* w1b = w1 + (size_t)e * HH * DD + (size_t)n0 * DD;
    const float* w3b = w3 + (size_t)e * HH * DD + (size_t)n0 * DD;

    auto load_stage = [&](int s, int k0) {
        float* As  = sm + s * SS1;
        float* B1s = As + BM * LDT;
        float* B3s = B1s + BN1 * LDT;
#pragma unroll
        for (int j = 0; j < 4; j++) {
            int c = tid + j * 256;
            int m = c >> 3, f = (c & 7) * 4;
            cp_async16(As + m * LDT + f, x + (size_t)tokSm[m] * DD + k0 + f);
        }
#pragma unroll
        for (int j = 0; j < 2; j++) {
            int c = tid + j * 256;
            int n = c >> 3, f = (c & 7) * 4;
            cp_async16(B1s + n * LDT + f, w1b + (size_t)n * DD + k0 + f);
            cp_async16(B3s + n * LDT + f, w3b + (size_t)n * DD + k0 + f);
        }
    };

#pragma unroll
    for (int s = 0; s < NST - 1; s++) { load_stage(s, s * BK); cp_commit(); }

    float c1[2][4][4], c3[2][4][4];
#pragma unroll
    for (int a = 0; a < 2; a++)
#pragma unroll
        for (int b = 0; b < 4; b++)
#pragma unroll
            for (int k = 0; k < 4; k++) { c1[a][b][k] = 0.f; c3[a][b][k] = 0.f; }

    int lane = tid & 31, wid = tid >> 5;
    int wm = (wid & 3) * 32;
    int wn = (wid >> 2) * 32;
    int g = lane >> 2, q = lane & 3;

    const int KT = DD / BK;
    for (int kt = 0; kt < KT; kt++) {
        int kn = kt + NST - 1;
        if (kn < KT) load_stage(kn % NST, kn * BK);
        cp_commit();
        cp_wait<NST - 1>();
        __syncthreads();
        const float* As  = sm + (kt % NST) * SS1;
        const float* B1s = As + BM * LDT;
        const float* B3s = B1s + BN1 * LDT;
#pragma unroll
        for (int ks = 0; ks < BK / 8; ks++) {
            int kb = ks * 8;
            uint32_t af[2][4], bf1[4][2], bf3[4][2];
#pragma unroll
            for (int mi = 0; mi < 2; mi++) {
                int r = wm + mi * 16 + g;
                af[mi][0] = f2tf(As[r * LDT + kb + q]);
                af[mi][1] = f2tf(As[(r + 8) * LDT + kb + q]);
                af[mi][2] = f2tf(As[r * LDT + kb + q + 4]);
                af[mi][3] = f2tf(As[(r + 8) * LDT + kb + q + 4]);
            }
#pragma unroll
            for (int ni = 0; ni < 4; ni++) {
                int nn = wn + ni * 8 + g;
                bf1[ni][0] = f2tf(B1s[nn * LDT + kb + q]);
                bf1[ni][1] = f2tf(B1s[nn * LDT + kb + q + 4]);
                bf3[ni][0] = f2tf(B3s[nn * LDT + kb + q]);
                bf3[ni][1] = f2tf(B3s[nn * LDT + kb + q + 4]);
            }
#pragma unroll
            for (int mi = 0; mi < 2; mi++)
#pragma unroll
                for (int ni = 0; ni < 4; ni++) {
                    mma8(c1[mi][ni], af[mi], bf1[ni]);
                    mma8(c3[mi][ni], af[mi], bf3[ni]);
                }
        }
        __syncthreads();
    }

    float* hid = g_hidden + (size_t)e * CAPC * HH;
#pragma unroll
    for (int mi = 0; mi < 2; mi++) {
        int r0 = m0 + wm + mi * 16 + g;
#pragma unroll
        for (int ni = 0; ni < 4; ni++) {
            int cb = n0 + wn + ni * 8 + q * 2;
            float2 v0, v1;
            v0.x = swiglu_act(c1[mi][ni][0], c3[mi][ni][0]);
            v0.y = swiglu_act(c1[mi][ni][1], c3[mi][ni][1]);
            v1.x = swiglu_act(c1[mi][ni][2], c3[mi][ni][2]);
            v1.y = swiglu_act(c1[mi][ni][3], c3[mi][ni][3]);
            *(float2*)(hid + (size_t)r0 * HH + cb)       = v0;
            *(float2*)(hid + (size_t)(r0 + 8) * HH + cb) = v1;
        }
    }
}

// ---------------- 4) GEMM2: y = (hidden @ W2^T) * slot_weight ----------------
#define BN2 128
#define SS2 ((BM + BN2) * LDT)

__global__ __launch_bounds__(256) void moe_gemm2(const float* __restrict__ w2) {
    int e = blockIdx.z;
    int cnt = g_cnt[e];
    int m0 = blockIdx.y * BM;
    if (m0 >= cnt) return;
    int n0 = blockIdx.x * BN2;

    extern __shared__ float sm[];
    int tid = threadIdx.x;
    const float* Ab = g_hidden + (size_t)e * CAPC * HH + (size_t)m0 * HH;
    const float* Bb = w2 + (size_t)e * DD * HH + (size_t)n0 * HH;

    auto load_stage = [&](int s, int k0) {
        float* As = sm + s * SS2;
        float* Bs = As + BM * LDT;
#pragma unroll
        for (int j = 0; j < 4; j++) {
            int c = tid + j * 256;
            int m = c >> 3, f = (c & 7) * 4;
            cp_async16(As + m * LDT + f, Ab + (size_t)m * HH + k0 + f);
        }
#pragma unroll
        for (int j = 0; j < 4; j++) {
            int c = tid + j * 256;
            int n = c >> 3, f = (c & 7) * 4;
            cp_async16(Bs + n * LDT + f, Bb + (size_t)n * HH + k0 + f);
        }
    };

#pragma unroll
    for (int s = 0; s < NST - 1; s++) { load_stage(s, s * BK); cp_commit(); }

    float cc[2][8][4];
#pragma unroll
    for (int a = 0; a < 2; a++)
#pragma unroll
        for (int b = 0; b < 8; b++)
#pragma unroll
            for (int k = 0; k < 4; k++) cc[a][b][k] = 0.f;

    int lane = tid & 31, wid = tid >> 5;
    int wm = (wid & 3) * 32;
    int wn = (wid >> 2) * 64;
    int g = lane >> 2, q = lane & 3;

    const int KT = HH / BK;
    for (int kt = 0; kt < KT; kt++) {
        int kn = kt + NST - 1;
        if (kn < KT) load_stage(kn % NST, kn * BK);
        cp_commit();
        cp_wait<NST - 1>();
        __syncthreads();
        const float* As = sm + (kt % NST) * SS2;
        const float* Bs = As + BM * LDT;
#pragma unroll
        for (int ks = 0; ks < BK / 8; ks++) {
            int kb = ks * 8;
            uint32_t af[2][4], bf[8][2];
#pragma unroll
            for (int mi = 0; mi < 2; mi++) {
                int r = wm + mi * 16 + g;
                af[mi][0] = f2tf(As[r * LDT + kb + q]);
                af[mi][1] = f2tf(As[(r + 8) * LDT + kb + q]);
                af[mi][2] = f2tf(As[r * LDT + kb + q + 4]);
                af[mi][3] = f2tf(As[(r + 8) * LDT + kb + q + 4]);
            }
#pragma unroll
            for (int ni = 0; ni < 8; ni++) {
                int nn = wn + ni * 8 + g;
                bf[ni][0] = f2tf(Bs[nn * LDT + kb + q]);
                bf[ni][1] = f2tf(Bs[nn * LDT + kb + q + 4]);
            }
#pragma unroll
            for (int mi = 0; mi < 2; mi++)
#pragma unroll
                for (int ni = 0; ni < 8; ni++)
                    mma8(cc[mi][ni], af[mi], bf[ni]);
        }
        __syncthreads();
    }

#pragma unroll
    for (int mi = 0; mi < 2; mi++) {
        int r0 = m0 + wm + mi * 16 + g;
        int r1 = r0 + 8;
        float wt0 = g_wslot[e * CAPC + r0];
        float wt1 = g_wslot[e * CAPC + r1];
#pragma unroll
        for (int ni = 0; ni < 8; ni++) {
            int cb = n0 + wn + ni * 8 + q * 2;
            float2 v0, v1;
            v0.x = cc[mi][ni][0] * wt0;
            v0.y = cc[mi][ni][1] * wt0;
            v1.x = cc[mi][ni][2] * wt1;
            v1.y = cc[mi][ni][3] * wt1;
            *(float2*)(g_y + ((size_t)(e * CAPC) + r0) * DD + cb) = v0;
            *(float2*)(g_y + ((size_t)(e * CAPC) + r1) * DD + cb) = v1;
        }
    }
}

// ---------------- 5) combine: out[t] = sum of token's surviving weighted y rows -----
__global__ __launch_bounds__(256) void moe_combine(float* __restrict__ out) {
    int t = blockIdx.x;
    int e0 = g_assign_e[2 * t],     p0 = g_assign_pos[2 * t];
    int e1 = g_assign_e[2 * t + 1], p1 = g_assign_pos[2 * t + 1];
    int d = threadIdx.x * 4;
    float4 acc = make_float4(0.f, 0.f, 0.f, 0.f);
    if (p0 >= 0) {
        float4 v = *(const float4*)(g_y + ((size_t)(e0 * CAPC + p0)) * DD + d);
        acc.x += v.x; acc.y += v.y; acc.z += v.z; acc.w += v.w;
    }
    if (p1 >= 0) {
        float4 v = *(const float4*)(g_y + ((size_t)(e1 * CAPC + p1)) * DD + d);
        acc.x += v.x; acc.y += v.y; acc.z += v.z; acc.w += v.w;
    }
    *(float4*)(out + (size_t)t * DD + d) = acc;
}

// ---------------- launcher ----------------
extern "C" void kernel_launch(void* const* d_in, const int* in_sizes, int n_in,
                              void* d_out, int out_size) {
    (void)in_sizes; (void)n_in; (void)out_size;
    const float* x  = (const float*)d_in[0];
    const float* wr = (const float*)d_in[1];
    const float* w1 = (const float*)d_in[2];
    const float* w3 = (const float*)d_in[3];
    const float* w2 = (const float*)d_in[4];
    float* out = (float*)d_out;

    static bool attr_done = false;
    if (!attr_done) {
        cudaFuncSetAttribute(moe_gemm1, cudaFuncAttributeMaxDynamicSharedMemorySize,
                             SS1 * NST * (int)sizeof(float));
        cudaFuncSetAttribute(moe_gemm2, cudaFuncAttributeMaxDynamicSharedMemorySize,
                             SS2 * NST * (int)sizeof(float));
        attr_done = true;
    }

    moe_router<<<AT / 8, 256>>>(x, wr);
    moe_sizes<<<1, 256>>>();
    moe_dispatch<<<EE, 256>>>();
    moe_gemm1<<<dim3(HH / BN1, CAPC / BM, EE), 256, SS1 * NST * (int)sizeof(float)>>>(x, w1, w3);
    moe_gemm2<<<dim3(DD / BN2, CAPC / BM, EE), 256, SS2 * NST * (int)sizeof(float)>>>(w2);
    moe_combine<<<AT, 256>>>(out);
}

// round 7
// speedup vs baseline: 1.0587x; 1.0587x over previous
#include <cuda_runtime.h>
#include <cstdint>

// ---------------- problem constants ----------------
#define AT   8192
#define DD   1024
#define EE   8
#define HH   2816
#define CAPC 2560
#define NASS (AT * 2)

// ---------------- scratch ----------------
__device__ int   g_assign_e[NASS];
__device__ float g_assign_w[NASS];
__device__ int   g_assign_pos[NASS];
__device__ int   g_tok[EE * CAPC];
__device__ float g_wslot[EE * CAPC];
__device__ int   g_cnt[EE];
__device__ int   g_lim[EE];
__device__ float g_hidden[(size_t)EE * CAPC * HH];   // tf32-rounded
__device__ float g_y[(size_t)EE * CAPC * DD];
__device__ float g_xc[(size_t)AT * DD];              // tf32-rounded x
__device__ float g_w1c[(size_t)EE * HH * DD];        // tf32-rounded weights (live experts)
__device__ float g_w3c[(size_t)EE * HH * DD];
__device__ float g_w2c[(size_t)EE * DD * HH];

// ---------------- helpers ----------------
__device__ __forceinline__ unsigned smem_u32(const void* p) {
    return (unsigned)__cvta_generic_to_shared(p);
}
__device__ __forceinline__ void cp_async16(void* dst, const void* src) {
    asm volatile("cp.async.cg.shared.global [%0], [%1], 16;\n"
                 :: "r"(smem_u32(dst)), "l"(src));
}
__device__ __forceinline__ void cp_commit() {
    asm volatile("cp.async.commit_group;\n");
}
template <int N>
__device__ __forceinline__ void cp_wait() {
    asm volatile("cp.async.wait_group %0;\n" :: "n"(N));
}
__device__ __forceinline__ uint32_t f2tf(float f) {
    uint32_t u;
    asm volatile("cvt.rna.tf32.f32 %0, %1;\n" : "=r"(u) : "f"(f));
    return u;
}
__device__ __forceinline__ float tf32r(float f) { return __uint_as_float(f2tf(f)); }
__device__ __forceinline__ void mma8(float* c, const uint32_t* a, const uint32_t* b) {
    asm volatile(
        "mma.sync.aligned.m16n8k8.row.col.f32.tf32.tf32.f32 "
        "{%0,%1,%2,%3}, {%4,%5,%6,%7}, {%8,%9}, {%0,%1,%2,%3};\n"
        : "+f"(c[0]), "+f"(c[1]), "+f"(c[2]), "+f"(c[3])
        : "r"(a[0]), "r"(a[1]), "r"(a[2]), "r"(a[3]), "r"(b[0]), "r"(b[1]));
}
__device__ __forceinline__ float swiglu_act(float a, float b) {
    return (a / (1.f + __expf(-a))) * b;
}

// ---------------- 1) router ----------------
__global__ __launch_bounds__(256) void moe_router(const float* __restrict__ x,
                                                  const float* __restrict__ wr) {
    __shared__ float ws[EE * DD];
    for (int i = threadIdx.x; i < EE * DD; i += 256) ws[i] = wr[i];
    __syncthreads();
    int lane = threadIdx.x & 31, w = threadIdx.x >> 5;
    int t = blockIdx.x * 8 + w;
    const float* xr = x + (size_t)t * DD;
    float acc[EE];
#pragma unroll
    for (int e = 0; e < EE; e++) acc[e] = 0.f;
    for (int d = lane; d < DD; d += 32) {
        float xv = xr[d];
#pragma unroll
        for (int e = 0; e < EE; e++) acc[e] += xv * ws[e * DD + d];
    }
#pragma unroll
    for (int off = 16; off > 0; off >>= 1) {
#pragma unroll
        for (int e = 0; e < EE; e++) acc[e] += __shfl_xor_sync(0xffffffffu, acc[e], off);
    }
    if (lane == 0) {
        float best = -1e30f, sec = -1e30f;
        int bi = 0, si = 0;
#pragma unroll
        for (int e = 0; e < EE; e++) {
            float l = acc[e];
            if (l > best) { sec = best; si = bi; best = l; bi = e; }
            else if (l > sec) { sec = l; si = e; }
        }
        float w0 = 1.f / (1.f + expf(sec - best));
        g_assign_e[2 * t]     = bi; g_assign_w[2 * t]     = w0;
        g_assign_e[2 * t + 1] = si; g_assign_w[2 * t + 1] = 1.f - w0;
    }
}

// ---------------- 1b) sizes: reference's rank-offset limits ----------------
__global__ void moe_sizes() {
    __shared__ int hist[EE];
    int tid = threadIdx.x;
    if (tid < EE) hist[tid] = 0;
    __syncthreads();
    for (int i = tid; i < NASS; i += blockDim.x) atomicAdd(&hist[g_assign_e[i]], 1);
    __syncthreads();
    if (tid == 0) {
        int S = 0, G = 0;
        for (int e = 0; e < EE; e++) {
            int sz = hist[e];
            int lim = 0;
            if (sz > 0) {
                G++;
                lim = CAPC - (S - G + 1);
                if (lim < 0) lim = 0;
                if (lim > CAPC) lim = CAPC;
            }
            g_lim[e] = lim;
            S += sz;
        }
    }
}

// ---------------- 2) dispatch ----------------
__global__ __launch_bounds__(256) void moe_dispatch() {
    int e = blockIdx.x;
    int tid = threadIdx.x;
    int lane = tid & 31, wid = tid >> 5;
    int lim = g_lim[e];
    __shared__ int warpsum[8];
    int carry = 0;
    for (int chunk = 0; chunk < NASS / 256; chunk++) {
        int i = chunk * 256 + tid;
        bool flag = (g_assign_e[i] == e);
        unsigned mask = __ballot_sync(0xffffffffu, flag);
        int wexcl = __popc(mask & ((1u << lane) - 1u));
        if (lane == 0) warpsum[wid] = __popc(mask);
        __syncthreads();
        int bexcl = 0, total = 0;
#pragma unroll
        for (int w = 0; w < 8; w++) {
            int s = warpsum[w];
            if (w < wid) bexcl += s;
            total += s;
        }
        if (flag) {
            int rank = carry + bexcl + wexcl;
            if (rank < lim) {
                g_tok[e * CAPC + rank]   = i >> 1;
                g_wslot[e * CAPC + rank] = g_assign_w[i];
                g_assign_pos[i] = rank;
            } else {
                g_assign_pos[i] = -1;
            }
        }
        carry += total;
        __syncthreads();
    }
    if (tid == 0) g_cnt[e] = carry < lim ? carry : lim;
}

// ---------------- 2b) tf32 pre-rounding (moves ALL cvt out of GEMM hot loops) ----
__global__ __launch_bounds__(256) void conv_x_k(const float* __restrict__ x) {
    int i = blockIdx.x * 256 + threadIdx.x;
    float4 v = ((const float4*)x)[i];
    float4 o;
    o.x = tf32r(v.x); o.y = tf32r(v.y); o.z = tf32r(v.z); o.w = tf32r(v.w);
    ((float4*)g_xc)[i] = o;
}
__global__ __launch_bounds__(256) void conv_w_k(const float* __restrict__ w1,
                                                const float* __restrict__ w3,
                                                const float* __restrict__ w2) {
    int e = blockIdx.y;
    if (g_cnt[e] == 0) return;                       // dead experts: skip entirely
    size_t idx = (size_t)e * (HH * (size_t)DD / 4) + blockIdx.x * 256 + threadIdx.x;
    float4 a = ((const float4*)w1)[idx];
    float4 b = ((const float4*)w3)[idx];
    float4 c = ((const float4*)w2)[idx];
    float4 oa, ob, oc;
    oa.x = tf32r(a.x); oa.y = tf32r(a.y); oa.z = tf32r(a.z); oa.w = tf32r(a.w);
    ob.x = tf32r(b.x); ob.y = tf32r(b.y); ob.z = tf32r(b.z); ob.w = tf32r(b.w);
    oc.x = tf32r(c.x); oc.y = tf32r(c.y); oc.z = tf32r(c.z); oc.w = tf32r(c.w);
    ((float4*)g_w1c)[idx] = oa;
    ((float4*)g_w3c)[idx] = ob;
    ((float4*)g_w2c)[idx] = oc;
}

// ---------------- 3) fused GEMM1 ----------------
#define BM   128
#define BN1  64
#define BK   32
#define LDT  36
#define NST  3
#define SS1  ((BM + 2 * BN1) * LDT)

__global__ __launch_bounds__(256) void moe_gemm1(const float* __restrict__ w1,
                                                 const float* __restrict__ w3) {
    int e = blockIdx.z;
    int cnt = g_cnt[e];
    int m0 = blockIdx.y * BM;
    if (m0 >= cnt) return;
    int n0 = blockIdx.x * BN1;

    extern __shared__ float sm[];
    __shared__ int tokSm[BM];
    int tid = threadIdx.x;
    for (int m = tid; m < BM; m += 256) {
        int r = m0 + m;
        if (r > cnt - 1) r = cnt - 1;
        tokSm[m] = g_tok[e * CAPC + r];
    }
    __syncthreads();

    const float* w1b = g_w1c + (size_t)e * HH * DD + (size_t)n0 * DD;
    const float* w3b = g_w3c + (size_t)e * HH * DD + (size_t)n0 * DD;

    auto load_stage = [&](int s, int k0) {
        float* As  = sm + s * SS1;
        float* B1s = As + BM * LDT;
        float* B3s = B1s + BN1 * LDT;
#pragma unroll
        for (int j = 0; j < 4; j++) {
            int c = tid + j * 256;
            int m = c >> 3, f = (c & 7) * 4;
            cp_async16(As + m * LDT + f, g_xc + (size_t)tokSm[m] * DD + k0 + f);
        }
#pragma unroll
        for (int j = 0; j < 2; j++) {
            int c = tid + j * 256;
            int n = c >> 3, f = (c & 7) * 4;
            cp_async16(B1s + n * LDT + f, w1b + (size_t)n * DD + k0 + f);
            cp_async16(B3s + n * LDT + f, w3b + (size_t)n * DD + k0 + f);
        }
    };

#pragma unroll
    for (int s = 0; s < NST - 1; s++) { load_stage(s, s * BK); cp_commit(); }

    float c1[2][4][4], c3[2][4][4];
#pragma unroll
    for (int a = 0; a < 2; a++)
#pragma unroll
        for (int b = 0; b < 4; b++)
#pragma unroll
            for (int k = 0; k < 4; k++) { c1[a][b][k] = 0.f; c3[a][b][k] = 0.f; }

    int lane = tid & 31, wid = tid >> 5;
    int wm = (wid & 3) * 32;
    int wn = (wid >> 2) * 32;
    int g = lane >> 2, q = lane & 3;

    const int KT = DD / BK;
    for (int kt = 0; kt < KT; kt++) {
        int kn = kt + NST - 1;
        if (kn < KT) load_stage(kn % NST, kn * BK);
        cp_commit();
        cp_wait<NST - 1>();
        __syncthreads();
        // operands pre-rounded to tf32 in memory: no cvt in the hot loop
        const uint32_t* As  = (const uint32_t*)(sm + (kt % NST) * SS1);
        const uint32_t* B1s = As + BM * LDT;
        const uint32_t* B3s = B1s + BN1 * LDT;
#pragma unroll
        for (int ks = 0; ks < BK / 8; ks++) {
            int kb = ks * 8;
            uint32_t af[2][4], bf1[4][2], bf3[4][2];
#pragma unroll
            for (int mi = 0; mi < 2; mi++) {
                int r = wm + mi * 16 + g;
                af[mi][0] = As[r * LDT + kb + q];
                af[mi][1] = As[(r + 8) * LDT + kb + q];
                af[mi][2] = As[r * LDT + kb + q + 4];
                af[mi][3] = As[(r + 8) * LDT + kb + q + 4];
            }
#pragma unroll
            for (int ni = 0; ni < 4; ni++) {
                int nn = wn + ni * 8 + g;
                bf1[ni][0] = B1s[nn * LDT + kb + q];
                bf1[ni][1] = B1s[nn * LDT + kb + q + 4];
                bf3[ni][0] = B3s[nn * LDT + kb + q];
                bf3[ni][1] = B3s[nn * LDT + kb + q + 4];
            }
#pragma unroll
            for (int mi = 0; mi < 2; mi++)
#pragma unroll
                for (int ni = 0; ni < 4; ni++) {
                    mma8(c1[mi][ni], af[mi], bf1[ni]);
                    mma8(c3[mi][ni], af[mi], bf3[ni]);
                }
        }
        __syncthreads();
    }

    // epilogue: hidden = tf32_round(silu(h1)*h3)  (ready as GEMM2 A-operand)
    float* hid = g_hidden + (size_t)e * CAPC * HH;
#pragma unroll
    for (int mi = 0; mi < 2; mi++) {
        int r0 = m0 + wm + mi * 16 + g;
#pragma unroll
        for (int ni = 0; ni < 4; ni++) {
            int cb = n0 + wn + ni * 8 + q * 2;
            float2 v0, v1;
            v0.x = tf32r(swiglu_act(c1[mi][ni][0], c3[mi][ni][0]));
            v0.y = tf32r(swiglu_act(c1[mi][ni][1], c3[mi][ni][1]));
            v1.x = tf32r(swiglu_act(c1[mi][ni][2], c3[mi][ni][2]));
            v1.y = tf32r(swiglu_act(c1[mi][ni][3], c3[mi][ni][3]));
            *(float2*)(hid + (size_t)r0 * HH + cb)       = v0;
            *(float2*)(hid + (size_t)(r0 + 8) * HH + cb) = v1;
        }
    }
}

// ---------------- 4) GEMM2 ----------------
#define BN2 128
#define SS2 ((BM + BN2) * LDT)

__global__ __launch_bounds__(256) void moe_gemm2() {
    int e = blockIdx.z;
    int cnt = g_cnt[e];
    int m0 = blockIdx.y * BM;
    if (m0 >= cnt) return;
    int n0 = blockIdx.x * BN2;

    extern __shared__ float sm[];
    int tid = threadIdx.x;
    const float* Ab = g_hidden + (size_t)e * CAPC * HH + (size_t)m0 * HH;
    const float* Bb = g_w2c + (size_t)e * DD * HH + (size_t)n0 * HH;

    auto load_stage = [&](int s, int k0) {
        float* As = sm + s * SS2;
        float* Bs = As + BM * LDT;
#pragma unroll
        for (int j = 0; j < 4; j++) {
            int c = tid + j * 256;
            int m = c >> 3, f = (c & 7) * 4;
            cp_async16(As + m * LDT + f, Ab + (size_t)m * HH + k0 + f);
        }
#pragma unroll
        for (int j = 0; j < 4; j++) {
            int c = tid + j * 256;
            int n = c >> 3, f = (c & 7) * 4;
            cp_async16(Bs + n * LDT + f, Bb + (size_t)n * HH + k0 + f);
        }
    };

#pragma unroll
    for (int s = 0; s < NST - 1; s++) { load_stage(s, s * BK); cp_commit(); }

    float cc[2][8][4];
#pragma unroll
    for (int a = 0; a < 2; a++)
#pragma unroll
        for (int b = 0; b < 8; b++)
#pragma unroll
            for (int k = 0; k < 4; k++) cc[a][b][k] = 0.f;

    int lane = tid & 31, wid = tid >> 5;
    int wm = (wid & 3) * 32;
    int wn = (wid >> 2) * 64;
    int g = lane >> 2, q = lane & 3;

    const int KT = HH / BK;
    for (int kt = 0; kt < KT; kt++) {
        int kn = kt + NST - 1;
        if (kn < KT) load_stage(kn % NST, kn * BK);
        cp_commit();
        cp_wait<NST - 1>();
        __syncthreads();
        const uint32_t* As = (const uint32_t*)(sm + (kt % NST) * SS2);
        const uint32_t* Bs = As + BM * LDT;
#pragma unroll
        for (int ks = 0; ks < BK / 8; ks++) {
            int kb = ks * 8;
            uint32_t af[2][4], bf[8][2];
#pragma unroll
            for (int mi = 0; mi < 2; mi++) {
                int r = wm + mi * 16 + g;
                af[mi][0] = As[r * LDT + kb + q];
                af[mi][1] = As[(r + 8) * LDT + kb + q];
                af[mi][2] = As[r * LDT + kb + q + 4];
                af[mi][3] = As[(r + 8) * LDT + kb + q + 4];
            }
#pragma unroll
            for (int ni = 0; ni < 8; ni++) {
                int nn = wn + ni * 8 + g;
                bf[ni][0] = Bs[nn * LDT + kb + q];
                bf[ni][1] = Bs[nn * LDT + kb + q + 4];
            }
#pragma unroll
            for (int mi = 0; mi < 2; mi++)
#pragma unroll
                for (int ni = 0; ni < 8; ni++)
                    mma8(cc[mi][ni], af[mi], bf[ni]);
        }
        __syncthreads();
    }

#pragma unroll
    for (int mi = 0; mi < 2; mi++) {
        int r0 = m0 + wm + mi * 16 + g;
        int r1 = r0 + 8;
        float wt0 = g_wslot[e * CAPC + r0];
        float wt1 = g_wslot[e * CAPC + r1];
#pragma unroll
        for (int ni = 0; ni < 8; ni++) {
            int cb = n0 + wn + ni * 8 + q * 2;
            float2 v0, v1;
            v0.x = cc[mi][ni][0] * wt0;
            v0.y = cc[mi][ni][1] * wt0;
            v1.x = cc[mi][ni][2] * wt1;
            v1.y = cc[mi][ni][3] * wt1;
            *(float2*)(g_y + ((size_t)(e * CAPC) + r0) * DD + cb) = v0;
            *(float2*)(g_y + ((size_t)(e * CAPC) + r1) * DD + cb) = v1;
        }
    }
}

// ---------------- 5) combine ----------------
__global__ __launch_bounds__(256) void moe_combine(float* __restrict__ out) {
    int t = blockIdx.x;
    int e0 = g_assign_e[2 * t],     p0 = g_assign_pos[2 * t];
    int e1 = g_assign_e[2 * t + 1], p1 = g_assign_pos[2 * t + 1];
    int d = threadIdx.x * 4;
    float4 acc = make_float4(0.f, 0.f, 0.f, 0.f);
    if (p0 >= 0) {
        float4 v = *(const float4*)(g_y + ((size_t)(e0 * CAPC + p0)) * DD + d);
        acc.x += v.x; acc.y += v.y; acc.z += v.z; acc.w += v.w;
    }
    if (p1 >= 0) {
        float4 v = *(const float4*)(g_y + ((size_t)(e1 * CAPC + p1)) * DD + d);
        acc.x += v.x; acc.y += v.y; acc.z += v.z; acc.w += v.w;
    }
    *(float4*)(out + (size_t)t * DD + d) = acc;
}

// ---------------- launcher ----------------
extern "C" void kernel_launch(void* const* d_in, const int* in_sizes, int n_in,
                              void* d_out, int out_size) {
    (void)in_sizes; (void)n_in; (void)out_size;
    const float* x  = (const float*)d_in[0];
    const float* wr = (const float*)d_in[1];
    const float* w1 = (const float*)d_in[2];
    const float* w3 = (const float*)d_in[3];
    const float* w2 = (const float*)d_in[4];
    float* out = (float*)d_out;

    static bool attr_done = false;
    if (!attr_done) {
        cudaFuncSetAttribute(moe_gemm1, cudaFuncAttributeMaxDynamicSharedMemorySize,
                             SS1 * NST * (int)sizeof(float));
        cudaFuncSetAttribute(moe_gemm2, cudaFuncAttributeMaxDynamicSharedMemorySize,
                             SS2 * NST * (int)sizeof(float));
        attr_done = true;
    }

    moe_router<<<AT / 8, 256>>>(x, wr);
    moe_sizes<<<1, 256>>>();
    moe_dispatch<<<EE, 256>>>();
    conv_x_k<<<AT * DD / 1024, 256>>>(x);
    conv_w_k<<<dim3(HH * DD / 1024, EE), 256>>>(w1, w3, w2);
    moe_gemm1<<<dim3(HH / BN1, CAPC / BM, EE), 256, SS1 * NST * (int)sizeof(float)>>>(w1, w3);
    moe_gemm2<<<dim3(DD / BN2, CAPC / BM, EE), 256, SS2 * NST * (int)sizeof(float)>>>();
    moe_combine<<<AT, 256>>>(out);
}